// round 13
// baseline (speedup 1.0000x reference)
#include <cuda_runtime.h>
#include <cuda_fp16.h>
#include <cstdint>
#include <cstddef>

#define Bz 1024
#define Tz 64
#define Dz 512
#define Hz 512
#define G4 2048
#define Kz 512

// ---------------- scratch (static __device__, allocation-free) ----------------
__device__ __align__(256) __half g_gx16[(size_t)Bz * Tz * G4];  // 256 MB x-gates (fp16, bias folded)
__device__ __align__(256) __half g_h2[2 * Bz * Hz];             // double-buffered fp16 h
__device__ __align__(256) __half g_wx[(size_t)Bz * Tz * Dz];    // 64 MB fp16 wx
__device__ __align__(256) __half g_wih[G4 * Dz];                // interleaved rows, fp16
__device__ __align__(256) __half g_whh[G4 * Hz];
__device__ __align__(256) float g_bias[G4];                     // interleaved cols
__device__ unsigned g_flag[128];                                // h producer flags
__device__ unsigned g_gxflag[8192];                             // gx tile flags (t,tb,bn)

#define N_XCTA 148                                              // x-GEMM worker CTAs

// ---------------- helpers ----------------
__device__ __forceinline__ uint32_t smem_u32(const void* p) {
    uint32_t a;
    asm("{ .reg .u64 t; cvta.to.shared.u64 t, %1; cvt.u32.u64 %0, t; }" : "=r"(a) : "l"(p));
    return a;
}
__device__ __forceinline__ unsigned ld_acq(const unsigned* p) {
    unsigned v;
    asm volatile("ld.acquire.gpu.global.u32 %0, [%1];" : "=r"(v) : "l"(p));
    return v;
}
__device__ __forceinline__ void red_rel_add(unsigned* p, unsigned v) {
    asm volatile("red.release.gpu.global.add.u32 [%0], %1;" :: "l"(p), "r"(v) : "memory");
}
__device__ __forceinline__ float frcp(float x) {
    float r;
    asm("rcp.approx.f32 %0, %1;" : "=f"(r) : "f"(x));
    return r;
}
__device__ __forceinline__ float sigm(float x) { return frcp(1.f + __expf(-x)); }
__device__ __forceinline__ float tanh_f(float x) { return fmaf(2.f, frcp(1.f + __expf(-2.f * x)), -1.f); }
__device__ __forceinline__ void st_cs_u32(void* p, uint32_t v) {
    asm volatile("st.global.cs.u32 [%0], %1;" :: "l"(p), "r"(v));
}
__device__ __forceinline__ void st_cs_f2(void* p, float a, float b) {
    asm volatile("st.global.cs.v2.f32 [%0], {%1, %2};" :: "l"(p), "f"(a), "f"(b));
}
__device__ __forceinline__ uint32_t pack_h2(float a, float b) {
    __half2 h = __floats2half2_rn(a, b);
    return *(uint32_t*)&h;
}

#define LDSM4(r, addr)                                                      \
    asm volatile("ldmatrix.sync.aligned.m8n8.x4.shared.b16 {%0,%1,%2,%3}, [%4];" \
                 : "=r"((r)[0]), "=r"((r)[1]), "=r"((r)[2]), "=r"((r)[3])   \
                 : "r"(addr))

#define MMA(d, a, b0, b1)                                                   \
    asm volatile("mma.sync.aligned.m16n8k16.row.col.f32.f16.f16.f32 "       \
                 "{%0,%1,%2,%3}, {%4,%5,%6,%7}, {%8,%9}, {%0,%1,%2,%3};"    \
                 : "+f"((d)[0]), "+f"((d)[1]), "+f"((d)[2]), "+f"((d)[3])   \
                 : "r"((a)[0]), "r"((a)[1]), "r"((a)[2]), "r"((a)[3]),      \
                   "r"(b0), "r"(b1))

#define CP_ASYNC16(s, g) \
    asm volatile("cp.async.cg.shared.global [%0], [%1], 16;" :: "r"(s), "l"(g))
#define CP_COMMIT() asm volatile("cp.async.commit_group;" ::: "memory")
#define CP_WAIT(n)  asm volatile("cp.async.wait_group %0;" :: "n"(n) : "memory")

// ---- smem: 3 stages of [A(8KB) | B(8KB)] swizzled pitch-64, + gx slice buffer ----
#define STG_SZ 16384
#define RGX_OFF (3 * STG_SZ)               // 49152
#define RGXP 272                           // gx pitch: 128 halves + 16B pad
#define K_SMEM (RGX_OFF + 128 * RGXP)      // 83968 (x2 = 164 KB/SM)

// ---------------- merged pre-pass: attn+wx | weight prep | state init ----------------
__global__ void __launch_bounds__(512)
pre_kernel(const float* __restrict__ x, const float* __restrict__ w_attn,
           float* __restrict__ out_w,
           const float* __restrict__ wih, const float* __restrict__ whh,
           const float* __restrict__ bih, const float* __restrict__ bhh) {
    const int bid = blockIdx.x;
    const int tid = threadIdx.x;

    if (bid < Bz) {
        // ---- attn = softmax_d( sum_t x[b,t,d]*w_x[t] ); wx = attn*x ----
        int b = bid, d = tid;
        __shared__ float wxs[Tz];
        __shared__ float red[Dz];
        if (d < Tz) wxs[d] = w_attn[2 * Hz + d];
        __syncthreads();
        const float* xb = x + (size_t)b * Tz * Dz + d;
        float acc = 0.f;
#pragma unroll 8
        for (int t = 0; t < Tz; t++) acc = fmaf(xb[(size_t)t * Dz], wxs[t], acc);
        red[d] = acc;
        __syncthreads();
        for (int s = 256; s > 0; s >>= 1) {
            if (d < s) red[d] = fmaxf(red[d], red[d + s]);
            __syncthreads();
        }
        float m = red[0];
        __syncthreads();
        float e = __expf(acc - m);
        red[d] = e;
        __syncthreads();
        for (int s = 256; s > 0; s >>= 1) {
            if (d < s) red[d] += red[d + s];
            __syncthreads();
        }
        float a = e / red[0];
        float* owb = out_w + (size_t)b * Tz * Dz + d;
        __half* wxb = g_wx + (size_t)b * Tz * Dz + d;
#pragma unroll 4
        for (int t = 0; t < Tz; t++) {
            float v = xb[(size_t)t * Dz] * a;
            owb[(size_t)t * Dz] = v;
            wxb[(size_t)t * Dz] = __float2half_rn(v);
        }
    } else if (bid < Bz + 2048) {
        // ---- weight prep: interleave rows (nr = (u/8)*32 + g*8 + u%8), fp16 ----
        int i = (bid - Bz) * 512 + tid;          // 0 .. 1M-1
        int row = i >> 9;
        int k = i & 511;
        int g = row >> 9;
        int u = row & 511;
        int nr = ((u >> 3) << 5) + (g << 3) + (u & 7);
        g_wih[nr * 512 + k] = __float2half_rn(wih[i]);
        g_whh[nr * 512 + k] = __float2half_rn(whh[i]);
        if (i < G4) {
            int gg = i >> 9, uu = i & 511;
            int nb = ((uu >> 3) << 5) + (gg << 3) + (uu & 7);
            g_bias[nb] = bih[i] + bhh[i];
        }
    } else {
        // ---- init h buffer 0 + flags ----
        int i = (bid - Bz - 2048) * 512 + tid;   // 0 .. Bz*Hz-1
        g_h2[i] = __float2half(0.f);
        if (i < 128) g_flag[i] = 0u;
        if (i < 8192) g_gxflag[i] = 0u;
    }
}

// ---------------- unified 128x128x512 mainloop (x workers) ----------------
__device__ __forceinline__ void mainloop(char* smem, int tid, int lane, int wm, int wn,
                                         const __half* Ab, long arst, const __half* Bb,
                                         float (&acc)[4][4][4]) {
    const int swl = (lane >> 1) & 3;
    const int swb = ((lane & 7) >> 1) & 3;

    auto pref = [&](int cj, int st) {
        int k0 = cj * 32;
        char* sb = smem + st * STG_SZ;
#pragma unroll
        for (int jj = 0; jj < 2; jj++) {
            int ci = tid * 2 + jj;
            int row = ci >> 2, c16 = ci & 3;
            int sw = (row >> 1) & 3;
            uint32_t soff = (uint32_t)(row * 64 + ((c16 ^ sw) << 4));
            CP_ASYNC16(smem_u32(sb + soff), Ab + (long)row * arst + k0 + c16 * 8);
            CP_ASYNC16(smem_u32(sb + 8192 + soff), Bb + (long)row * 512 + k0 + c16 * 8);
        }
    };

    pref(0, 0);
    CP_COMMIT();
    pref(1, 1);
    CP_COMMIT();

#pragma unroll
    for (int a = 0; a < 4; a++)
#pragma unroll
        for (int b = 0; b < 4; b++)
#pragma unroll
            for (int c = 0; c < 4; c++) acc[a][b][c] = 0.f;

    int stage = 0;
    for (int j = 0; j < 16; j++) {
        if (j < 15) { CP_WAIT(1); } else { CP_WAIT(0); }
        __syncthreads();
        if (j + 2 < 16) {
            int ns = stage + 2;
            if (ns >= 3) ns -= 3;
            pref(j + 2, ns);
            CP_COMMIT();
        }
        char* sa = smem + stage * STG_SZ;
#pragma unroll
        for (int kk = 0; kk < 2; kk++) {
            uint32_t av[4][4], bq[2][4];
#pragma unroll
            for (int mi = 0; mi < 4; mi++) {
                int row = wm * 64 + (lane & 15) + mi * 16;
                int c16 = (lane >> 4) + kk * 2;
                LDSM4(av[mi], smem_u32(sa + row * 64 + ((c16 ^ swl) << 4)));
            }
#pragma unroll
            for (int p = 0; p < 2; p++) {
                int row = wn * 32 + (lane >> 4) * 8 + (lane & 7) + p * 16;
                int c16 = kk * 2 + ((lane >> 3) & 1);
                LDSM4(bq[p], smem_u32(sa + 8192 + row * 64 + ((c16 ^ swb) << 4)));
            }
#pragma unroll
            for (int mi = 0; mi < 4; mi++)
#pragma unroll
                for (int ni = 0; ni < 4; ni++)
                    MMA(acc[mi][ni], av[mi], bq[ni >> 1][(ni & 1) * 2], bq[ni >> 1][(ni & 1) * 2 + 1]);
        }
        if (++stage == 3) stage = 0;
    }
    __syncthreads();
}

// ---------------- heterogeneous persistent kernel: 128 rec CTAs + 148 gemx CTAs ----------------
__global__ void __launch_bounds__(256, 2)
fused_enc(float* __restrict__ out_enc) {
    extern __shared__ char smem[];
    const int tid = threadIdx.x;
    const int lane = tid & 31, wid = tid >> 5;
    const int wm = wid >> 2, wn = wid & 3;
    const int bid = blockIdx.x;

    float acc[4][4][4];

    if (bid >= 128) {
        // ================= x-GEMM worker: t-major gx tiles =================
        for (int idx = bid - 128; idx < 8192; idx += N_XCTA) {
            int t = idx >> 7;
            int r = idx & 127;
            int tb = r >> 4, bnx = r & 15;

            const __half* A = g_wx + ((size_t)(tb * 128) * Tz + t) * Dz;
            const __half* B = g_wih + (size_t)bnx * 128 * 512;
            mainloop(smem, tid, lane, wm, wn, A, (long)Tz * Dz, B, acc);

#pragma unroll
            for (int ni = 0; ni < 4; ni++) {
                int c = bnx * 128 + wn * 32 + ni * 8 + (lane & 3) * 2;
                float2 bi = *(const float2*)(g_bias + c);
#pragma unroll
                for (int mi = 0; mi < 4; mi++) {
                    int rloc = wm * 64 + mi * 16 + (lane >> 2);
                    size_t r0 = ((size_t)(tb * 128 + rloc) * Tz + t) * G4 + c;
                    size_t r1 = ((size_t)(tb * 128 + rloc + 8) * Tz + t) * G4 + c;
                    st_cs_u32(g_gx16 + r0, pack_h2(acc[mi][ni][0] + bi.x, acc[mi][ni][1] + bi.y));
                    st_cs_u32(g_gx16 + r1, pack_h2(acc[mi][ni][2] + bi.x, acc[mi][ni][3] + bi.y));
                }
            }
            __syncthreads();
            if (tid == 0) red_rel_add(&g_gxflag[idx], 1u);
        }
        return;
    }

    // ================= persistent recurrence CTA =================
    const int bn = bid & 15, bm = bid >> 4;
    const int U = (bn * 4 + wn) * 8 + (lane & 3) * 2;
    const __half* Bh = g_whh + (size_t)bn * 128 * 512;
    const int swl = (lane >> 1) & 3;
    const int swb = ((lane & 7) >> 1) & 3;

    auto pref_gx = [&](int t) {
        char* gb = smem + RGX_OFF;
#pragma unroll
        for (int q = 0; q < 8; q++) {
            int ci = tid + q * 256;
            int row = ci >> 4, c = ci & 15;
            const void* g = g_gx16 + ((size_t)(bm * 128 + row) * Tz + t) * G4 + bn * 128 + c * 8;
            CP_ASYNC16(smem_u32(gb + row * RGXP + c * 16), g);
        }
    };

    float c_reg[4][2][2];
#pragma unroll
    for (int mi = 0; mi < 4; mi++)
#pragma unroll
        for (int h = 0; h < 2; h++) { c_reg[mi][h][0] = 0.f; c_reg[mi][h][1] = 0.f; }

    for (int t = 0; t < Tz; t++) {
        // ---- wait for this step's gx tile ----
        if (tid == 0) {
            while (ld_acq(&g_gxflag[t * 128 + bm * 16 + bn]) == 0) { }
        }
        __syncthreads();

        const __half* A = g_h2 + (size_t)(t & 1) * Bz * Hz + (size_t)bm * 128 * Hz;
        auto pref_h = [&](int cj, int st) {
            int k0 = cj * 32;
            char* sb = smem + st * STG_SZ;
#pragma unroll
            for (int jj = 0; jj < 2; jj++) {
                int ci = tid * 2 + jj;
                int row = ci >> 2, c16 = ci & 3;
                int sw = (row >> 1) & 3;
                uint32_t soff = (uint32_t)(row * 64 + ((c16 ^ sw) << 4));
                CP_ASYNC16(smem_u32(sb + soff), A + (size_t)row * Hz + k0 + c16 * 8);
                CP_ASYNC16(smem_u32(sb + 8192 + soff), Bh + (long)row * 512 + k0 + c16 * 8);
            }
        };

        // group 1: gx slice + own h chunk (bn) — own flag always current, zero wait
        pref_gx(t);
        pref_h(bn, 0);
        CP_COMMIT();
        // chunk bn+1: fine-grained wait on its single producer
        if (t && tid == 0) {
            while (ld_acq(&g_flag[bm * 16 + ((bn + 1) & 15)]) < (unsigned)t) { }
        }
        __syncthreads();
        pref_h((bn + 1) & 15, 1);
        CP_COMMIT();

#pragma unroll
        for (int a = 0; a < 4; a++)
#pragma unroll
            for (int b = 0; b < 4; b++)
#pragma unroll
                for (int c = 0; c < 4; c++) acc[a][b][c] = 0.f;

        int stage = 0;
        for (int j = 0; j < 16; j++) {
            if (j < 15) { CP_WAIT(1); } else { CP_WAIT(0); }
            // per-chunk producer wait folded between cp-wait and barrier: no extra sync
            if (t && tid == 0 && j + 2 < 16) {
                while (ld_acq(&g_flag[bm * 16 + ((bn + j + 2) & 15)]) < (unsigned)t) { }
            }
            __syncthreads();
            if (j + 2 < 16) {
                int ns = stage + 2;
                if (ns >= 3) ns -= 3;
                pref_h((bn + j + 2) & 15, ns);
                CP_COMMIT();
            }
            char* sa = smem + stage * STG_SZ;
#pragma unroll
            for (int kk = 0; kk < 2; kk++) {
                uint32_t av[4][4], bq[2][4];
#pragma unroll
                for (int mi = 0; mi < 4; mi++) {
                    int row = wm * 64 + (lane & 15) + mi * 16;
                    int c16 = (lane >> 4) + kk * 2;
                    LDSM4(av[mi], smem_u32(sa + row * 64 + ((c16 ^ swl) << 4)));
                }
#pragma unroll
                for (int p = 0; p < 2; p++) {
                    int row = wn * 32 + (lane >> 4) * 8 + (lane & 7) + p * 16;
                    int c16 = kk * 2 + ((lane >> 3) & 1);
                    LDSM4(bq[p], smem_u32(sa + 8192 + row * 64 + ((c16 ^ swb) << 4)));
                }
#pragma unroll
                for (int mi = 0; mi < 4; mi++)
#pragma unroll
                    for (int ni = 0; ni < 4; ni++)
                        MMA(acc[mi][ni], av[mi], bq[ni >> 1][(ni & 1) * 2], bq[ni >> 1][(ni & 1) * 2 + 1]);
            }
            if (++stage == 3) stage = 0;
        }

        // ---- fused LSTM epilogue (gx from smem, c in registers) ----
        __half* hw = g_h2 + (size_t)((t + 1) & 1) * Bz * Hz;
        char* gb = smem + RGX_OFF;
#pragma unroll
        for (int mi = 0; mi < 4; mi++) {
#pragma unroll
            for (int half = 0; half < 2; half++) {
                int mloc = wm * 64 + mi * 16 + half * 8 + (lane >> 2);
                int m = bm * 128 + mloc;
                int j0 = half * 2;
                const __half* gxr = (const __half*)(gb + mloc * RGXP) + wn * 32 + (lane & 3) * 2;
                float2 gI = __half22float2(*(const __half2*)(gxr + 0));
                float2 gF = __half22float2(*(const __half2*)(gxr + 8));
                float2 gG = __half22float2(*(const __half2*)(gxr + 16));
                float2 gO = __half22float2(*(const __half2*)(gxr + 24));
                float gi0 = acc[mi][0][j0] + gI.x, gi1 = acc[mi][0][j0 + 1] + gI.y;
                float gf0 = acc[mi][1][j0] + gF.x, gf1 = acc[mi][1][j0 + 1] + gF.y;
                float gg0 = acc[mi][2][j0] + gG.x, gg1 = acc[mi][2][j0 + 1] + gG.y;
                float go0 = acc[mi][3][j0] + gO.x, go1 = acc[mi][3][j0 + 1] + gO.y;
                float c20 = sigm(gf0) * c_reg[mi][half][0] + sigm(gi0) * tanh_f(gg0);
                float c21 = sigm(gf1) * c_reg[mi][half][1] + sigm(gi1) * tanh_f(gg1);
                c_reg[mi][half][0] = c20;
                c_reg[mi][half][1] = c21;
                float h20 = sigm(go0) * tanh_f(c20);
                float h21 = sigm(go1) * tanh_f(c21);
                st_cs_f2(out_enc + ((size_t)m * Tz + t) * Hz + U, h20, h21);
                *(__half2*)(hw + (size_t)m * Hz + U) =
                    __half2(__float2half_rn(h20), __float2half_rn(h21));
            }
        }

        // ---- publish h(t+1): syncthreads + release-atomic (no threadfence) ----
        __syncthreads();
        if (tid == 0) red_rel_add(&g_flag[bm * 16 + bn], 1u);
    }
}

// ---------------- launch ----------------
extern "C" void kernel_launch(void* const* d_in, const int* in_sizes, int n_in,
                              void* d_out, int out_size) {
    const float* x      = (const float*)d_in[0];
    const float* w_ih   = (const float*)d_in[1];
    const float* w_hh   = (const float*)d_in[2];
    const float* b_ih   = (const float*)d_in[3];
    const float* b_hh   = (const float*)d_in[4];
    const float* w_attn = (const float*)d_in[5];
    (void)in_sizes; (void)n_in; (void)out_size;

    float* out_w   = (float*)d_out;
    float* out_enc = out_w + (size_t)Bz * Tz * Dz;

    static int attr_done = 0;
    if (!attr_done) {
        cudaFuncSetAttribute(fused_enc, cudaFuncAttributeMaxDynamicSharedMemorySize, K_SMEM);
        attr_done = 1;
    }

    // merged pre-pass: attn+wx (1024) | weight prep (2048) | init (1024)
    pre_kernel<<<Bz + 2048 + 1024, 512>>>(x, w_attn, out_w, w_ih, w_hh, b_ih, b_hh);

    // heterogeneous persistent kernel: x-GEMM workers + recurrence, co-resident
    fused_enc<<<128 + N_XCTA, 256, K_SMEM>>>(out_enc);
}

// round 14
// speedup vs baseline: 1.1859x; 1.1859x over previous
#include <cuda_runtime.h>
#include <cuda_fp16.h>
#include <cstdint>
#include <cstddef>

#define Bz 1024
#define Tz 64
#define Dz 512
#define Hz 512
#define G4 2048
#define Kz 512

// ---------------- scratch (static __device__, allocation-free) ----------------
__device__ __align__(256) __half g_gx16[(size_t)Bz * Tz * G4];  // 256 MB x-gates (fp16, bias folded)
__device__ __align__(256) __half g_h2[2 * Bz * Hz];             // double-buffered fp16 h
__device__ __align__(256) __half g_wx[(size_t)Bz * Tz * Dz];    // 64 MB fp16 wx
__device__ __align__(256) __half g_wih[G4 * Dz];                // interleaved rows, fp16
__device__ __align__(256) __half g_whh[G4 * Hz];
__device__ __align__(256) float g_bias[G4];                     // interleaved cols
__device__ unsigned g_flag[128];                                // h producer flags
__device__ unsigned g_gxflag[8192];                             // gx tile flags (t,tb,bn)

#define N_XCTA 168                                              // x-GEMM worker CTAs (grid 296 = 2/SM exactly)

// ---------------- helpers ----------------
__device__ __forceinline__ uint32_t smem_u32(const void* p) {
    uint32_t a;
    asm("{ .reg .u64 t; cvta.to.shared.u64 t, %1; cvt.u32.u64 %0, t; }" : "=r"(a) : "l"(p));
    return a;
}
__device__ __forceinline__ unsigned ld_acq(const unsigned* p) {
    unsigned v;
    asm volatile("ld.acquire.gpu.global.u32 %0, [%1];" : "=r"(v) : "l"(p));
    return v;
}
__device__ __forceinline__ void red_rel_add(unsigned* p, unsigned v) {
    asm volatile("red.release.gpu.global.add.u32 [%0], %1;" :: "l"(p), "r"(v) : "memory");
}
__device__ __forceinline__ float frcp(float x) {
    float r;
    asm("rcp.approx.f32 %0, %1;" : "=f"(r) : "f"(x));
    return r;
}
__device__ __forceinline__ float sigm(float x) { return frcp(1.f + __expf(-x)); }
__device__ __forceinline__ float tanh_f(float x) { return fmaf(2.f, frcp(1.f + __expf(-2.f * x)), -1.f); }
__device__ __forceinline__ void st_cs_u32(void* p, uint32_t v) {
    asm volatile("st.global.cs.u32 [%0], %1;" :: "l"(p), "r"(v));
}
__device__ __forceinline__ void st_cs_f2(void* p, float a, float b) {
    asm volatile("st.global.cs.v2.f32 [%0], {%1, %2};" :: "l"(p), "f"(a), "f"(b));
}
__device__ __forceinline__ uint32_t pack_h2(float a, float b) {
    __half2 h = __floats2half2_rn(a, b);
    return *(uint32_t*)&h;
}

#define LDSM4(r, addr)                                                      \
    asm volatile("ldmatrix.sync.aligned.m8n8.x4.shared.b16 {%0,%1,%2,%3}, [%4];" \
                 : "=r"((r)[0]), "=r"((r)[1]), "=r"((r)[2]), "=r"((r)[3])   \
                 : "r"(addr))

#define MMA(d, a, b0, b1)                                                   \
    asm volatile("mma.sync.aligned.m16n8k16.row.col.f32.f16.f16.f32 "       \
                 "{%0,%1,%2,%3}, {%4,%5,%6,%7}, {%8,%9}, {%0,%1,%2,%3};"    \
                 : "+f"((d)[0]), "+f"((d)[1]), "+f"((d)[2]), "+f"((d)[3])   \
                 : "r"((a)[0]), "r"((a)[1]), "r"((a)[2]), "r"((a)[3]),      \
                   "r"(b0), "r"(b1))

#define CP_ASYNC16(s, g) \
    asm volatile("cp.async.cg.shared.global [%0], [%1], 16;" :: "r"(s), "l"(g))
#define CP_COMMIT() asm volatile("cp.async.commit_group;" ::: "memory")
#define CP_WAIT(n)  asm volatile("cp.async.wait_group %0;" :: "n"(n) : "memory")

// ---- smem: 3 stages of [A(8KB) | B(8KB)] swizzled pitch-64, + gx slice buffer ----
#define STG_SZ 16384
#define RGX_OFF (3 * STG_SZ)               // 49152
#define RGXP 272                           // gx pitch: 128 halves + 16B pad
#define K_SMEM (RGX_OFF + 128 * RGXP)      // 83968 (x2 = 164 KB/SM)

// ---------------- merged pre-pass: attn+wx | weight prep | state init ----------------
__global__ void __launch_bounds__(512)
pre_kernel(const float* __restrict__ x, const float* __restrict__ w_attn,
           float* __restrict__ out_w,
           const float* __restrict__ wih, const float* __restrict__ whh,
           const float* __restrict__ bih, const float* __restrict__ bhh) {
    const int bid = blockIdx.x;
    const int tid = threadIdx.x;

    if (bid < Bz) {
        // ---- attn = softmax_d( sum_t x[b,t,d]*w_x[t] ); wx = attn*x ----
        int b = bid, d = tid;
        __shared__ float wxs[Tz];
        __shared__ float red[Dz];
        if (d < Tz) wxs[d] = w_attn[2 * Hz + d];
        __syncthreads();
        const float* xb = x + (size_t)b * Tz * Dz + d;
        float acc = 0.f;
#pragma unroll 8
        for (int t = 0; t < Tz; t++) acc = fmaf(xb[(size_t)t * Dz], wxs[t], acc);
        red[d] = acc;
        __syncthreads();
        for (int s = 256; s > 0; s >>= 1) {
            if (d < s) red[d] = fmaxf(red[d], red[d + s]);
            __syncthreads();
        }
        float m = red[0];
        __syncthreads();
        float e = __expf(acc - m);
        red[d] = e;
        __syncthreads();
        for (int s = 256; s > 0; s >>= 1) {
            if (d < s) red[d] += red[d + s];
            __syncthreads();
        }
        float a = e / red[0];
        float* owb = out_w + (size_t)b * Tz * Dz + d;
        __half* wxb = g_wx + (size_t)b * Tz * Dz + d;
#pragma unroll 4
        for (int t = 0; t < Tz; t++) {
            float v = xb[(size_t)t * Dz] * a;
            owb[(size_t)t * Dz] = v;
            wxb[(size_t)t * Dz] = __float2half_rn(v);
        }
    } else if (bid < Bz + 2048) {
        // ---- weight prep: interleave rows (nr = (u/8)*32 + g*8 + u%8), fp16 ----
        int i = (bid - Bz) * 512 + tid;          // 0 .. 1M-1
        int row = i >> 9;
        int k = i & 511;
        int g = row >> 9;
        int u = row & 511;
        int nr = ((u >> 3) << 5) + (g << 3) + (u & 7);
        g_wih[nr * 512 + k] = __float2half_rn(wih[i]);
        g_whh[nr * 512 + k] = __float2half_rn(whh[i]);
        if (i < G4) {
            int gg = i >> 9, uu = i & 511;
            int nb = ((uu >> 3) << 5) + (gg << 3) + (uu & 7);
            g_bias[nb] = bih[i] + bhh[i];
        }
    } else {
        // ---- init h buffer 0 + flags ----
        int i = (bid - Bz - 2048) * 512 + tid;   // 0 .. Bz*Hz-1
        g_h2[i] = __float2half(0.f);
        if (i < 128) g_flag[i] = 0u;
        if (i < 8192) g_gxflag[i] = 0u;
    }
}

// ---------------- unified 128x128x512 mainloop (x workers) ----------------
__device__ __forceinline__ void mainloop(char* smem, int tid, int lane, int wm, int wn,
                                         const __half* Ab, long arst, const __half* Bb,
                                         float (&acc)[4][4][4]) {
    const int swl = (lane >> 1) & 3;
    const int swb = ((lane & 7) >> 1) & 3;

    auto pref = [&](int cj, int st) {
        int k0 = cj * 32;
        char* sb = smem + st * STG_SZ;
#pragma unroll
        for (int jj = 0; jj < 2; jj++) {
            int ci = tid * 2 + jj;
            int row = ci >> 2, c16 = ci & 3;
            int sw = (row >> 1) & 3;
            uint32_t soff = (uint32_t)(row * 64 + ((c16 ^ sw) << 4));
            CP_ASYNC16(smem_u32(sb + soff), Ab + (long)row * arst + k0 + c16 * 8);
            CP_ASYNC16(smem_u32(sb + 8192 + soff), Bb + (long)row * 512 + k0 + c16 * 8);
        }
    };

    pref(0, 0);
    CP_COMMIT();
    pref(1, 1);
    CP_COMMIT();

#pragma unroll
    for (int a = 0; a < 4; a++)
#pragma unroll
        for (int b = 0; b < 4; b++)
#pragma unroll
            for (int c = 0; c < 4; c++) acc[a][b][c] = 0.f;

    int stage = 0;
    for (int j = 0; j < 16; j++) {
        if (j < 15) { CP_WAIT(1); } else { CP_WAIT(0); }
        __syncthreads();
        if (j + 2 < 16) {
            int ns = stage + 2;
            if (ns >= 3) ns -= 3;
            pref(j + 2, ns);
            CP_COMMIT();
        }
        char* sa = smem + stage * STG_SZ;
#pragma unroll
        for (int kk = 0; kk < 2; kk++) {
            uint32_t av[4][4], bq[2][4];
#pragma unroll
            for (int mi = 0; mi < 4; mi++) {
                int row = wm * 64 + (lane & 15) + mi * 16;
                int c16 = (lane >> 4) + kk * 2;
                LDSM4(av[mi], smem_u32(sa + row * 64 + ((c16 ^ swl) << 4)));
            }
#pragma unroll
            for (int p = 0; p < 2; p++) {
                int row = wn * 32 + (lane >> 4) * 8 + (lane & 7) + p * 16;
                int c16 = kk * 2 + ((lane >> 3) & 1);
                LDSM4(bq[p], smem_u32(sa + 8192 + row * 64 + ((c16 ^ swb) << 4)));
            }
#pragma unroll
            for (int mi = 0; mi < 4; mi++)
#pragma unroll
                for (int ni = 0; ni < 4; ni++)
                    MMA(acc[mi][ni], av[mi], bq[ni >> 1][(ni & 1) * 2], bq[ni >> 1][(ni & 1) * 2 + 1]);
        }
        if (++stage == 3) stage = 0;
    }
    __syncthreads();
}

// ---------------- heterogeneous persistent kernel: 128 rec CTAs + 168 gemx CTAs ----------------
__global__ void __launch_bounds__(256, 2)
fused_enc(float* __restrict__ out_enc) {
    extern __shared__ char smem[];
    const int tid = threadIdx.x;
    const int lane = tid & 31, wid = tid >> 5;
    const int wm = wid >> 2, wn = wid & 3;
    const int bid = blockIdx.x;

    float acc[4][4][4];

    if (bid >= 128) {
        // ================= x-GEMM worker: t-major gx tiles =================
        for (int idx = bid - 128; idx < 8192; idx += N_XCTA) {
            int t = idx >> 7;
            int r = idx & 127;
            int tb = r >> 4, bnx = r & 15;

            const __half* A = g_wx + ((size_t)(tb * 128) * Tz + t) * Dz;
            const __half* B = g_wih + (size_t)bnx * 128 * 512;
            mainloop(smem, tid, lane, wm, wn, A, (long)Tz * Dz, B, acc);

#pragma unroll
            for (int ni = 0; ni < 4; ni++) {
                int c = bnx * 128 + wn * 32 + ni * 8 + (lane & 3) * 2;
                float2 bi = *(const float2*)(g_bias + c);
#pragma unroll
                for (int mi = 0; mi < 4; mi++) {
                    int rloc = wm * 64 + mi * 16 + (lane >> 2);
                    size_t r0 = ((size_t)(tb * 128 + rloc) * Tz + t) * G4 + c;
                    size_t r1 = ((size_t)(tb * 128 + rloc + 8) * Tz + t) * G4 + c;
                    st_cs_u32(g_gx16 + r0, pack_h2(acc[mi][ni][0] + bi.x, acc[mi][ni][1] + bi.y));
                    st_cs_u32(g_gx16 + r1, pack_h2(acc[mi][ni][2] + bi.x, acc[mi][ni][3] + bi.y));
                }
            }
            __syncthreads();
            if (tid == 0) red_rel_add(&g_gxflag[idx], 1u);
        }
        return;
    }

    // ================= persistent recurrence CTA =================
    const int bn = bid & 15, bm = bid >> 4;
    const int U = (bn * 4 + wn) * 8 + (lane & 3) * 2;
    const __half* Bh = g_whh + (size_t)bn * 128 * 512;
    const int swl = (lane >> 1) & 3;
    const int swb = ((lane & 7) >> 1) & 3;

    auto pref_gx = [&](int t) {
        char* gb = smem + RGX_OFF;
#pragma unroll
        for (int q = 0; q < 8; q++) {
            int ci = tid + q * 256;
            int row = ci >> 4, c = ci & 15;
            const void* g = g_gx16 + ((size_t)(bm * 128 + row) * Tz + t) * G4 + bn * 128 + c * 8;
            CP_ASYNC16(smem_u32(gb + row * RGXP + c * 16), g);
        }
    };

    float c_reg[4][2][2];
#pragma unroll
    for (int mi = 0; mi < 4; mi++)
#pragma unroll
        for (int h = 0; h < 2; h++) { c_reg[mi][h][0] = 0.f; c_reg[mi][h][1] = 0.f; }

    for (int t = 0; t < Tz; t++) {
        // ---- wait for this step's gx tile, then stage it ----
        if (tid == 0) {
            while (ld_acq(&g_gxflag[t * 128 + bm * 16 + bn]) == 0) { }
        }
        __syncthreads();
        pref_gx(t);
        CP_COMMIT();

        // ---- bulk wait for h(t) producers of this bm group (16 parallel spins) ----
        if (t) {
            if (tid < 16) {
                while (ld_acq(&g_flag[bm * 16 + tid]) < (unsigned)t) { }
            }
            __syncthreads();
        }

        // ---- h-GEMM: acc = h(t) @ W_hh'^T, 3-stage pipeline ----
        const __half* A = g_h2 + (size_t)(t & 1) * Bz * Hz + (size_t)bm * 128 * Hz;
        auto pref_h = [&](int cj, int st) {
            int k0 = cj * 32;
            char* sb = smem + st * STG_SZ;
#pragma unroll
            for (int jj = 0; jj < 2; jj++) {
                int ci = tid * 2 + jj;
                int row = ci >> 2, c16 = ci & 3;
                int sw = (row >> 1) & 3;
                uint32_t soff = (uint32_t)(row * 64 + ((c16 ^ sw) << 4));
                CP_ASYNC16(smem_u32(sb + soff), A + (size_t)row * Hz + k0 + c16 * 8);
                CP_ASYNC16(smem_u32(sb + 8192 + soff), Bh + (long)row * 512 + k0 + c16 * 8);
            }
        };

        pref_h(bn, 0);
        CP_COMMIT();
        pref_h((bn + 1) & 15, 1);
        CP_COMMIT();

#pragma unroll
        for (int a = 0; a < 4; a++)
#pragma unroll
            for (int b = 0; b < 4; b++)
#pragma unroll
                for (int c = 0; c < 4; c++) acc[a][b][c] = 0.f;

        int stage = 0;
        for (int j = 0; j < 16; j++) {
            if (j < 15) { CP_WAIT(1); } else { CP_WAIT(0); }
            __syncthreads();
            if (j + 2 < 16) {
                int ns = stage + 2;
                if (ns >= 3) ns -= 3;
                pref_h((bn + j + 2) & 15, ns);
                CP_COMMIT();
            }
            char* sa = smem + stage * STG_SZ;
#pragma unroll
            for (int kk = 0; kk < 2; kk++) {
                uint32_t av[4][4], bq[2][4];
#pragma unroll
                for (int mi = 0; mi < 4; mi++) {
                    int row = wm * 64 + (lane & 15) + mi * 16;
                    int c16 = (lane >> 4) + kk * 2;
                    LDSM4(av[mi], smem_u32(sa + row * 64 + ((c16 ^ swl) << 4)));
                }
#pragma unroll
                for (int p = 0; p < 2; p++) {
                    int row = wn * 32 + (lane >> 4) * 8 + (lane & 7) + p * 16;
                    int c16 = kk * 2 + ((lane >> 3) & 1);
                    LDSM4(bq[p], smem_u32(sa + 8192 + row * 64 + ((c16 ^ swb) << 4)));
                }
#pragma unroll
                for (int mi = 0; mi < 4; mi++)
#pragma unroll
                    for (int ni = 0; ni < 4; ni++)
                        MMA(acc[mi][ni], av[mi], bq[ni >> 1][(ni & 1) * 2], bq[ni >> 1][(ni & 1) * 2 + 1]);
            }
            if (++stage == 3) stage = 0;
        }

        // ---- fused LSTM epilogue (gx from smem, c in registers) ----
        __half* hw = g_h2 + (size_t)((t + 1) & 1) * Bz * Hz;
        char* gb = smem + RGX_OFF;
#pragma unroll
        for (int mi = 0; mi < 4; mi++) {
#pragma unroll
            for (int half = 0; half < 2; half++) {
                int mloc = wm * 64 + mi * 16 + half * 8 + (lane >> 2);
                int m = bm * 128 + mloc;
                int j0 = half * 2;
                const __half* gxr = (const __half*)(gb + mloc * RGXP) + wn * 32 + (lane & 3) * 2;
                float2 gI = __half22float2(*(const __half2*)(gxr + 0));
                float2 gF = __half22float2(*(const __half2*)(gxr + 8));
                float2 gG = __half22float2(*(const __half2*)(gxr + 16));
                float2 gO = __half22float2(*(const __half2*)(gxr + 24));
                float gi0 = acc[mi][0][j0] + gI.x, gi1 = acc[mi][0][j0 + 1] + gI.y;
                float gf0 = acc[mi][1][j0] + gF.x, gf1 = acc[mi][1][j0 + 1] + gF.y;
                float gg0 = acc[mi][2][j0] + gG.x, gg1 = acc[mi][2][j0 + 1] + gG.y;
                float go0 = acc[mi][3][j0] + gO.x, go1 = acc[mi][3][j0 + 1] + gO.y;
                float c20 = sigm(gf0) * c_reg[mi][half][0] + sigm(gi0) * tanh_f(gg0);
                float c21 = sigm(gf1) * c_reg[mi][half][1] + sigm(gi1) * tanh_f(gg1);
                c_reg[mi][half][0] = c20;
                c_reg[mi][half][1] = c21;
                float h20 = sigm(go0) * tanh_f(c20);
                float h21 = sigm(go1) * tanh_f(c21);
                st_cs_f2(out_enc + ((size_t)m * Tz + t) * Hz + U, h20, h21);
                *(__half2*)(hw + (size_t)m * Hz + U) =
                    __half2(__float2half_rn(h20), __float2half_rn(h21));
            }
        }

        // ---- publish h(t+1): syncthreads + release-atomic ----
        __syncthreads();
        if (tid == 0) red_rel_add(&g_flag[bm * 16 + bn], 1u);
    }
}

// ---------------- launch ----------------
extern "C" void kernel_launch(void* const* d_in, const int* in_sizes, int n_in,
                              void* d_out, int out_size) {
    const float* x      = (const float*)d_in[0];
    const float* w_ih   = (const float*)d_in[1];
    const float* w_hh   = (const float*)d_in[2];
    const float* b_ih   = (const float*)d_in[3];
    const float* b_hh   = (const float*)d_in[4];
    const float* w_attn = (const float*)d_in[5];
    (void)in_sizes; (void)n_in; (void)out_size;

    float* out_w   = (float*)d_out;
    float* out_enc = out_w + (size_t)Bz * Tz * Dz;

    static int attr_done = 0;
    if (!attr_done) {
        cudaFuncSetAttribute(fused_enc, cudaFuncAttributeMaxDynamicSharedMemorySize, K_SMEM);
        attr_done = 1;
    }

    // merged pre-pass: attn+wx (1024) | weight prep (2048) | init (1024)
    pre_kernel<<<Bz + 2048 + 1024, 512>>>(x, w_attn, out_w, w_ih, w_hh, b_ih, b_hh);

    // heterogeneous persistent kernel: x-GEMM workers + recurrence, co-resident
    fused_enc<<<128 + N_XCTA, 256, K_SMEM>>>(out_enc);
}

// round 15
// speedup vs baseline: 1.2118x; 1.0218x over previous
#include <cuda_runtime.h>
#include <cuda_fp16.h>
#include <cstdint>
#include <cstddef>

#define Bz 1024
#define Tz 64
#define Dz 512
#define Hz 512
#define G4 2048
#define Kz 512

// ---------------- scratch (static __device__, allocation-free) ----------------
__device__ __align__(256) __half g_gx16[(size_t)Bz * Tz * G4];  // 256 MB x-gates (fp16, bias folded)
__device__ __align__(256) __half g_h2[2 * Bz * Hz];             // double-buffered fp16 h
__device__ __align__(256) __half g_wx[(size_t)Bz * Tz * Dz];    // 64 MB fp16 wx
__device__ __align__(256) __half g_wih[G4 * Dz];                // interleaved rows, fp16
__device__ __align__(256) __half g_whh[G4 * Hz];
__device__ __align__(256) float g_bias[G4];                     // interleaved cols
__device__ unsigned g_flag[128];                                // h producer flags
__device__ unsigned g_gxflag[8192];                             // gx tile flags (t,tb,bn)

#define N_XCTA 168                                              // x-GEMM worker CTAs (grid 296 = 2/SM exactly)

// ---------------- helpers ----------------
__device__ __forceinline__ uint32_t smem_u32(const void* p) {
    uint32_t a;
    asm("{ .reg .u64 t; cvta.to.shared.u64 t, %1; cvt.u32.u64 %0, t; }" : "=r"(a) : "l"(p));
    return a;
}
__device__ __forceinline__ unsigned ld_acq(const unsigned* p) {
    unsigned v;
    asm volatile("ld.acquire.gpu.global.u32 %0, [%1];" : "=r"(v) : "l"(p));
    return v;
}
__device__ __forceinline__ void red_rel_add(unsigned* p, unsigned v) {
    asm volatile("red.release.gpu.global.add.u32 [%0], %1;" :: "l"(p), "r"(v) : "memory");
}
// HW tanh (sm_75+): single MUFU op
__device__ __forceinline__ float tanh_f(float x) {
    float r;
    asm("tanh.approx.f32 %0, %1;" : "=f"(r) : "f"(x));
    return r;
}
// sigmoid via HW tanh: sigm(x) = 0.5*tanh(x/2) + 0.5  (1 MUFU + FFMA)
__device__ __forceinline__ float sigm(float x) {
    return fmaf(tanh_f(0.5f * x), 0.5f, 0.5f);
}
__device__ __forceinline__ void st_cs_u32(void* p, uint32_t v) {
    asm volatile("st.global.cs.u32 [%0], %1;" :: "l"(p), "r"(v));
}
__device__ __forceinline__ void st_cs_f2(void* p, float a, float b) {
    asm volatile("st.global.cs.v2.f32 [%0], {%1, %2};" :: "l"(p), "f"(a), "f"(b));
}
__device__ __forceinline__ uint32_t pack_h2(float a, float b) {
    __half2 h = __floats2half2_rn(a, b);
    return *(uint32_t*)&h;
}

#define LDSM4(r, addr)                                                      \
    asm volatile("ldmatrix.sync.aligned.m8n8.x4.shared.b16 {%0,%1,%2,%3}, [%4];" \
                 : "=r"((r)[0]), "=r"((r)[1]), "=r"((r)[2]), "=r"((r)[3])   \
                 : "r"(addr))

#define MMA(d, a, b0, b1)                                                   \
    asm volatile("mma.sync.aligned.m16n8k16.row.col.f32.f16.f16.f32 "       \
                 "{%0,%1,%2,%3}, {%4,%5,%6,%7}, {%8,%9}, {%0,%1,%2,%3};"    \
                 : "+f"((d)[0]), "+f"((d)[1]), "+f"((d)[2]), "+f"((d)[3])   \
                 : "r"((a)[0]), "r"((a)[1]), "r"((a)[2]), "r"((a)[3]),      \
                   "r"(b0), "r"(b1))

#define CP_ASYNC16(s, g) \
    asm volatile("cp.async.cg.shared.global [%0], [%1], 16;" :: "r"(s), "l"(g))
#define CP_COMMIT() asm volatile("cp.async.commit_group;" ::: "memory")
#define CP_WAIT(n)  asm volatile("cp.async.wait_group %0;" :: "n"(n) : "memory")

// ---- smem: 3 stages of [A(8KB) | B(8KB)] swizzled pitch-64, + gx slice buffer ----
#define STG_SZ 16384
#define RGX_OFF (3 * STG_SZ)               // 49152
#define RGXP 272                           // gx pitch: 128 halves + 16B pad
#define K_SMEM (RGX_OFF + 128 * RGXP)      // 83968 (x2 = 164 KB/SM)

// ---------------- merged pre-pass: attn+wx | weight prep | state init ----------------
__global__ void __launch_bounds__(512)
pre_kernel(const float* __restrict__ x, const float* __restrict__ w_attn,
           float* __restrict__ out_w,
           const float* __restrict__ wih, const float* __restrict__ whh,
           const float* __restrict__ bih, const float* __restrict__ bhh) {
    const int bid = blockIdx.x;
    const int tid = threadIdx.x;

    if (bid < Bz) {
        // ---- attn = softmax_d( sum_t x[b,t,d]*w_x[t] ); wx = attn*x ----
        int b = bid, d = tid;
        __shared__ float wxs[Tz];
        __shared__ float red[Dz];
        if (d < Tz) wxs[d] = w_attn[2 * Hz + d];
        __syncthreads();
        const float* xb = x + (size_t)b * Tz * Dz + d;
        float acc = 0.f;
#pragma unroll 8
        for (int t = 0; t < Tz; t++) acc = fmaf(xb[(size_t)t * Dz], wxs[t], acc);
        red[d] = acc;
        __syncthreads();
        for (int s = 256; s > 0; s >>= 1) {
            if (d < s) red[d] = fmaxf(red[d], red[d + s]);
            __syncthreads();
        }
        float m = red[0];
        __syncthreads();
        float e = __expf(acc - m);
        red[d] = e;
        __syncthreads();
        for (int s = 256; s > 0; s >>= 1) {
            if (d < s) red[d] += red[d + s];
            __syncthreads();
        }
        float a = e / red[0];
        float* owb = out_w + (size_t)b * Tz * Dz + d;
        __half* wxb = g_wx + (size_t)b * Tz * Dz + d;
#pragma unroll 4
        for (int t = 0; t < Tz; t++) {
            float v = xb[(size_t)t * Dz] * a;
            owb[(size_t)t * Dz] = v;
            wxb[(size_t)t * Dz] = __float2half_rn(v);
        }
    } else if (bid < Bz + 2048) {
        // ---- weight prep: interleave rows (nr = (u/8)*32 + g*8 + u%8), fp16 ----
        int i = (bid - Bz) * 512 + tid;          // 0 .. 1M-1
        int row = i >> 9;
        int k = i & 511;
        int g = row >> 9;
        int u = row & 511;
        int nr = ((u >> 3) << 5) + (g << 3) + (u & 7);
        g_wih[nr * 512 + k] = __float2half_rn(wih[i]);
        g_whh[nr * 512 + k] = __float2half_rn(whh[i]);
        if (i < G4) {
            int gg = i >> 9, uu = i & 511;
            int nb = ((uu >> 3) << 5) + (gg << 3) + (uu & 7);
            g_bias[nb] = bih[i] + bhh[i];
        }
    } else {
        // ---- init h buffer 0 + flags ----
        int i = (bid - Bz - 2048) * 512 + tid;   // 0 .. Bz*Hz-1
        g_h2[i] = __float2half(0.f);
        if (i < 128) g_flag[i] = 0u;
        if (i < 8192) g_gxflag[i] = 0u;
    }
}

// ---------------- unified 128x128x512 mainloop (x workers) ----------------
__device__ __forceinline__ void mainloop(char* smem, int tid, int lane, int wm, int wn,
                                         const __half* Ab, long arst, const __half* Bb,
                                         float (&acc)[4][4][4]) {
    const int swl = (lane >> 1) & 3;
    const int swb = ((lane & 7) >> 1) & 3;

    auto pref = [&](int cj, int st) {
        int k0 = cj * 32;
        char* sb = smem + st * STG_SZ;
#pragma unroll
        for (int jj = 0; jj < 2; jj++) {
            int ci = tid * 2 + jj;
            int row = ci >> 2, c16 = ci & 3;
            int sw = (row >> 1) & 3;
            uint32_t soff = (uint32_t)(row * 64 + ((c16 ^ sw) << 4));
            CP_ASYNC16(smem_u32(sb + soff), Ab + (long)row * arst + k0 + c16 * 8);
            CP_ASYNC16(smem_u32(sb + 8192 + soff), Bb + (long)row * 512 + k0 + c16 * 8);
        }
    };

    pref(0, 0);
    CP_COMMIT();
    pref(1, 1);
    CP_COMMIT();

#pragma unroll
    for (int a = 0; a < 4; a++)
#pragma unroll
        for (int b = 0; b < 4; b++)
#pragma unroll
            for (int c = 0; c < 4; c++) acc[a][b][c] = 0.f;

    int stage = 0;
    for (int j = 0; j < 16; j++) {
        if (j < 15) { CP_WAIT(1); } else { CP_WAIT(0); }
        __syncthreads();
        if (j + 2 < 16) {
            int ns = stage + 2;
            if (ns >= 3) ns -= 3;
            pref(j + 2, ns);
            CP_COMMIT();
        }
        char* sa = smem + stage * STG_SZ;
#pragma unroll
        for (int kk = 0; kk < 2; kk++) {
            uint32_t av[4][4], bq[2][4];
#pragma unroll
            for (int mi = 0; mi < 4; mi++) {
                int row = wm * 64 + (lane & 15) + mi * 16;
                int c16 = (lane >> 4) + kk * 2;
                LDSM4(av[mi], smem_u32(sa + row * 64 + ((c16 ^ swl) << 4)));
            }
#pragma unroll
            for (int p = 0; p < 2; p++) {
                int row = wn * 32 + (lane >> 4) * 8 + (lane & 7) + p * 16;
                int c16 = kk * 2 + ((lane >> 3) & 1);
                LDSM4(bq[p], smem_u32(sa + 8192 + row * 64 + ((c16 ^ swb) << 4)));
            }
#pragma unroll
            for (int mi = 0; mi < 4; mi++)
#pragma unroll
                for (int ni = 0; ni < 4; ni++)
                    MMA(acc[mi][ni], av[mi], bq[ni >> 1][(ni & 1) * 2], bq[ni >> 1][(ni & 1) * 2 + 1]);
        }
        if (++stage == 3) stage = 0;
    }
    __syncthreads();
}

// ---------------- heterogeneous persistent kernel: 128 rec CTAs + 168 gemx CTAs ----------------
__global__ void __launch_bounds__(256, 2)
fused_enc(float* __restrict__ out_enc) {
    extern __shared__ char smem[];
    const int tid = threadIdx.x;
    const int lane = tid & 31, wid = tid >> 5;
    const int wm = wid >> 2, wn = wid & 3;
    const int bid = blockIdx.x;

    float acc[4][4][4];

    if (bid >= 128) {
        // ================= x-GEMM worker: t-major gx tiles =================
        for (int idx = bid - 128; idx < 8192; idx += N_XCTA) {
            int t = idx >> 7;
            int r = idx & 127;
            int tb = r >> 4, bnx = r & 15;

            const __half* A = g_wx + ((size_t)(tb * 128) * Tz + t) * Dz;
            const __half* B = g_wih + (size_t)bnx * 128 * 512;
            mainloop(smem, tid, lane, wm, wn, A, (long)Tz * Dz, B, acc);

#pragma unroll
            for (int ni = 0; ni < 4; ni++) {
                int c = bnx * 128 + wn * 32 + ni * 8 + (lane & 3) * 2;
                float2 bi = *(const float2*)(g_bias + c);
#pragma unroll
                for (int mi = 0; mi < 4; mi++) {
                    int rloc = wm * 64 + mi * 16 + (lane >> 2);
                    size_t r0 = ((size_t)(tb * 128 + rloc) * Tz + t) * G4 + c;
                    size_t r1 = ((size_t)(tb * 128 + rloc + 8) * Tz + t) * G4 + c;
                    st_cs_u32(g_gx16 + r0, pack_h2(acc[mi][ni][0] + bi.x, acc[mi][ni][1] + bi.y));
                    st_cs_u32(g_gx16 + r1, pack_h2(acc[mi][ni][2] + bi.x, acc[mi][ni][3] + bi.y));
                }
            }
            __syncthreads();
            if (tid == 0) red_rel_add(&g_gxflag[idx], 1u);
        }
        return;
    }

    // ================= persistent recurrence CTA =================
    const int bn = bid & 15, bm = bid >> 4;
    const int U = (bn * 4 + wn) * 8 + (lane & 3) * 2;
    const __half* Bh = g_whh + (size_t)bn * 128 * 512;
    const int swl = (lane >> 1) & 3;
    const int swb = ((lane & 7) >> 1) & 3;

    auto pref_gx = [&](int t) {
        char* gb = smem + RGX_OFF;
#pragma unroll
        for (int q = 0; q < 8; q++) {
            int ci = tid + q * 256;
            int row = ci >> 4, c = ci & 15;
            const void* g = g_gx16 + ((size_t)(bm * 128 + row) * Tz + t) * G4 + bn * 128 + c * 8;
            CP_ASYNC16(smem_u32(gb + row * RGXP + c * 16), g);
        }
    };

    float c_reg[4][2][2];
#pragma unroll
    for (int mi = 0; mi < 4; mi++)
#pragma unroll
        for (int h = 0; h < 2; h++) { c_reg[mi][h][0] = 0.f; c_reg[mi][h][1] = 0.f; }

    for (int t = 0; t < Tz; t++) {
        // ---- wait for this step's gx tile, then stage it ----
        if (tid == 0) {
            while (ld_acq(&g_gxflag[t * 128 + bm * 16 + bn]) == 0) { }
        }
        __syncthreads();
        pref_gx(t);
        CP_COMMIT();

        // ---- bulk wait for h(t) producers of this bm group (16 parallel spins) ----
        if (t) {
            if (tid < 16) {
                while (ld_acq(&g_flag[bm * 16 + tid]) < (unsigned)t) { }
            }
            __syncthreads();
        }

        // ---- h-GEMM: acc = h(t) @ W_hh'^T, 3-stage pipeline ----
        const __half* A = g_h2 + (size_t)(t & 1) * Bz * Hz + (size_t)bm * 128 * Hz;
        auto pref_h = [&](int cj, int st) {
            int k0 = cj * 32;
            char* sb = smem + st * STG_SZ;
#pragma unroll
            for (int jj = 0; jj < 2; jj++) {
                int ci = tid * 2 + jj;
                int row = ci >> 2, c16 = ci & 3;
                int sw = (row >> 1) & 3;
                uint32_t soff = (uint32_t)(row * 64 + ((c16 ^ sw) << 4));
                CP_ASYNC16(smem_u32(sb + soff), A + (size_t)row * Hz + k0 + c16 * 8);
                CP_ASYNC16(smem_u32(sb + 8192 + soff), Bh + (long)row * 512 + k0 + c16 * 8);
            }
        };

        pref_h(bn, 0);
        CP_COMMIT();
        pref_h((bn + 1) & 15, 1);
        CP_COMMIT();

#pragma unroll
        for (int a = 0; a < 4; a++)
#pragma unroll
            for (int b = 0; b < 4; b++)
#pragma unroll
                for (int c = 0; c < 4; c++) acc[a][b][c] = 0.f;

        int stage = 0;
        for (int j = 0; j < 16; j++) {
            if (j < 15) { CP_WAIT(1); } else { CP_WAIT(0); }
            __syncthreads();
            if (j + 2 < 16) {
                int ns = stage + 2;
                if (ns >= 3) ns -= 3;
                pref_h((bn + j + 2) & 15, ns);
                CP_COMMIT();
            }
            char* sa = smem + stage * STG_SZ;
#pragma unroll
            for (int kk = 0; kk < 2; kk++) {
                uint32_t av[4][4], bq[2][4];
#pragma unroll
                for (int mi = 0; mi < 4; mi++) {
                    int row = wm * 64 + (lane & 15) + mi * 16;
                    int c16 = (lane >> 4) + kk * 2;
                    LDSM4(av[mi], smem_u32(sa + row * 64 + ((c16 ^ swl) << 4)));
                }
#pragma unroll
                for (int p = 0; p < 2; p++) {
                    int row = wn * 32 + (lane >> 4) * 8 + (lane & 7) + p * 16;
                    int c16 = kk * 2 + ((lane >> 3) & 1);
                    LDSM4(bq[p], smem_u32(sa + 8192 + row * 64 + ((c16 ^ swb) << 4)));
                }
#pragma unroll
                for (int mi = 0; mi < 4; mi++)
#pragma unroll
                    for (int ni = 0; ni < 4; ni++)
                        MMA(acc[mi][ni], av[mi], bq[ni >> 1][(ni & 1) * 2], bq[ni >> 1][(ni & 1) * 2 + 1]);
            }
            if (++stage == 3) stage = 0;
        }

        // ---- fused LSTM epilogue (gx from smem, c in registers, HW tanh) ----
        __half* hw = g_h2 + (size_t)((t + 1) & 1) * Bz * Hz;
        char* gb = smem + RGX_OFF;
#pragma unroll
        for (int mi = 0; mi < 4; mi++) {
#pragma unroll
            for (int half = 0; half < 2; half++) {
                int mloc = wm * 64 + mi * 16 + half * 8 + (lane >> 2);
                int m = bm * 128 + mloc;
                int j0 = half * 2;
                const __half* gxr = (const __half*)(gb + mloc * RGXP) + wn * 32 + (lane & 3) * 2;
                float2 gI = __half22float2(*(const __half2*)(gxr + 0));
                float2 gF = __half22float2(*(const __half2*)(gxr + 8));
                float2 gG = __half22float2(*(const __half2*)(gxr + 16));
                float2 gO = __half22float2(*(const __half2*)(gxr + 24));
                float gi0 = acc[mi][0][j0] + gI.x, gi1 = acc[mi][0][j0 + 1] + gI.y;
                float gf0 = acc[mi][1][j0] + gF.x, gf1 = acc[mi][1][j0 + 1] + gF.y;
                float gg0 = acc[mi][2][j0] + gG.x, gg1 = acc[mi][2][j0 + 1] + gG.y;
                float go0 = acc[mi][3][j0] + gO.x, go1 = acc[mi][3][j0 + 1] + gO.y;
                float c20 = sigm(gf0) * c_reg[mi][half][0] + sigm(gi0) * tanh_f(gg0);
                float c21 = sigm(gf1) * c_reg[mi][half][1] + sigm(gi1) * tanh_f(gg1);
                c_reg[mi][half][0] = c20;
                c_reg[mi][half][1] = c21;
                float h20 = sigm(go0) * tanh_f(c20);
                float h21 = sigm(go1) * tanh_f(c21);
                st_cs_f2(out_enc + ((size_t)m * Tz + t) * Hz + U, h20, h21);
                *(__half2*)(hw + (size_t)m * Hz + U) =
                    __half2(__float2half_rn(h20), __float2half_rn(h21));
            }
        }

        // ---- publish h(t+1): syncthreads + release-atomic ----
        __syncthreads();
        if (tid == 0) red_rel_add(&g_flag[bm * 16 + bn], 1u);
    }
}

// ---------------- launch ----------------
extern "C" void kernel_launch(void* const* d_in, const int* in_sizes, int n_in,
                              void* d_out, int out_size) {
    const float* x      = (const float*)d_in[0];
    const float* w_ih   = (const float*)d_in[1];
    const float* w_hh   = (const float*)d_in[2];
    const float* b_ih   = (const float*)d_in[3];
    const float* b_hh   = (const float*)d_in[4];
    const float* w_attn = (const float*)d_in[5];
    (void)in_sizes; (void)n_in; (void)out_size;

    float* out_w   = (float*)d_out;
    float* out_enc = out_w + (size_t)Bz * Tz * Dz;

    static int attr_done = 0;
    if (!attr_done) {
        cudaFuncSetAttribute(fused_enc, cudaFuncAttributeMaxDynamicSharedMemorySize, K_SMEM);
        attr_done = 1;
    }

    // merged pre-pass: attn+wx (1024) | weight prep (2048) | init (1024)
    pre_kernel<<<Bz + 2048 + 1024, 512>>>(x, w_attn, out_w, w_ih, w_hh, b_ih, b_hh);

    // heterogeneous persistent kernel: x-GEMM workers + recurrence, co-resident
    fused_enc<<<128 + N_XCTA, 256, K_SMEM>>>(out_enc);
}

// round 17
// speedup vs baseline: 1.2149x; 1.0026x over previous
#include <cuda_runtime.h>
#include <cuda_fp16.h>
#include <cstdint>
#include <cstddef>

#define Bz 1024
#define Tz 64
#define Dz 512
#define Hz 512
#define G4 2048
#define Kz 512

// ---------------- scratch (static __device__, allocation-free) ----------------
__device__ __align__(256) __half g_gx16[(size_t)Bz * Tz * G4];  // 256 MB x-gates (fp16, bias folded)
__device__ __align__(256) __half g_h2[2 * Bz * Hz];             // double-buffered fp16 h
__device__ __align__(256) __half g_wx[(size_t)Bz * Tz * Dz];    // 64 MB fp16 wx
__device__ __align__(256) __half g_wih[G4 * Dz];                // interleaved rows, fp16
__device__ __align__(256) __half g_whh[G4 * Hz];
__device__ __align__(256) float g_bias[G4];                     // interleaved cols
__device__ unsigned g_flag[128];                                // h producer flags
__device__ unsigned g_gxflag[8192];                             // gx tile flags (t,tb,bn)

#define N_XCTA 168                                              // x-GEMM worker CTAs (grid 296 = 2/SM exactly)

// ---------------- helpers ----------------
__device__ __forceinline__ uint32_t smem_u32(const void* p) {
    uint32_t a;
    asm("{ .reg .u64 t; cvta.to.shared.u64 t, %1; cvt.u32.u64 %0, t; }" : "=r"(a) : "l"(p));
    return a;
}
__device__ __forceinline__ unsigned ld_acq(const unsigned* p) {
    unsigned v;
    asm volatile("ld.acquire.gpu.global.u32 %0, [%1];" : "=r"(v) : "l"(p));
    return v;
}
__device__ __forceinline__ void red_rel_add(unsigned* p, unsigned v) {
    asm volatile("red.release.gpu.global.add.u32 [%0], %1;" :: "l"(p), "r"(v) : "memory");
}
// HW tanh (sm_75+): single MUFU op
__device__ __forceinline__ float tanh_f(float x) {
    float r;
    asm("tanh.approx.f32 %0, %1;" : "=f"(r) : "f"(x));
    return r;
}
// sigmoid via HW tanh: sigm(x) = 0.5*tanh(x/2) + 0.5  (1 MUFU + FFMA)
__device__ __forceinline__ float sigm(float x) {
    return fmaf(tanh_f(0.5f * x), 0.5f, 0.5f);
}
__device__ __forceinline__ void st_cs_u32(void* p, uint32_t v) {
    asm volatile("st.global.cs.u32 [%0], %1;" :: "l"(p), "r"(v));
}
__device__ __forceinline__ void st_cs_f2(void* p, float a, float b) {
    asm volatile("st.global.cs.v2.f32 [%0], {%1, %2};" :: "l"(p), "f"(a), "f"(b));
}
__device__ __forceinline__ uint32_t pack_h2(float a, float b) {
    __half2 h = __floats2half2_rn(a, b);
    return *(uint32_t*)&h;
}

#define LDSM4(r, addr)                                                      \
    asm volatile("ldmatrix.sync.aligned.m8n8.x4.shared.b16 {%0,%1,%2,%3}, [%4];" \
                 : "=r"((r)[0]), "=r"((r)[1]), "=r"((r)[2]), "=r"((r)[3])   \
                 : "r"(addr))

#define MMA(d, a, b0, b1)                                                   \
    asm volatile("mma.sync.aligned.m16n8k16.row.col.f32.f16.f16.f32 "       \
                 "{%0,%1,%2,%3}, {%4,%5,%6,%7}, {%8,%9}, {%0,%1,%2,%3};"    \
                 : "+f"((d)[0]), "+f"((d)[1]), "+f"((d)[2]), "+f"((d)[3])   \
                 : "r"((a)[0]), "r"((a)[1]), "r"((a)[2]), "r"((a)[3]),      \
                   "r"(b0), "r"(b1))

#define CP_ASYNC16(s, g) \
    asm volatile("cp.async.cg.shared.global [%0], [%1], 16;" :: "r"(s), "l"(g))
#define CP_COMMIT() asm volatile("cp.async.commit_group;" ::: "memory")
#define CP_WAIT(n)  asm volatile("cp.async.wait_group %0;" :: "n"(n) : "memory")

// ---- smem: 3 stages [A|B] + OWN buffer [A|B] + gx slice ----
#define STG_SZ 16384
#define OWN_OFF (3 * STG_SZ)               // 49152 (A: own h chunk, B: W_hh chunk bn resident)
#define RGX_OFF (OWN_OFF + STG_SZ)         // 65536
#define RGXP 272                           // gx pitch: 128 halves + 16B pad
#define K_SMEM (RGX_OFF + 128 * RGXP)      // 100352 (x2 = 196 KB/SM)

// ---------------- merged pre-pass: attn+wx | weight prep | state init ----------------
__global__ void __launch_bounds__(512)
pre_kernel(const float* __restrict__ x, const float* __restrict__ w_attn,
           float* __restrict__ out_w,
           const float* __restrict__ wih, const float* __restrict__ whh,
           const float* __restrict__ bih, const float* __restrict__ bhh) {
    const int bid = blockIdx.x;
    const int tid = threadIdx.x;

    if (bid < Bz) {
        // ---- attn = softmax_d( sum_t x[b,t,d]*w_x[t] ); wx = attn*x ----
        int b = bid, d = tid;
        __shared__ float wxs[Tz];
        __shared__ float red[Dz];
        if (d < Tz) wxs[d] = w_attn[2 * Hz + d];
        __syncthreads();
        const float* xb = x + (size_t)b * Tz * Dz + d;
        float acc = 0.f;
#pragma unroll 8
        for (int t = 0; t < Tz; t++) acc = fmaf(xb[(size_t)t * Dz], wxs[t], acc);
        red[d] = acc;
        __syncthreads();
        for (int s = 256; s > 0; s >>= 1) {
            if (d < s) red[d] = fmaxf(red[d], red[d + s]);
            __syncthreads();
        }
        float m = red[0];
        __syncthreads();
        float e = __expf(acc - m);
        red[d] = e;
        __syncthreads();
        for (int s = 256; s > 0; s >>= 1) {
            if (d < s) red[d] += red[d + s];
            __syncthreads();
        }
        float a = e / red[0];
        float* owb = out_w + (size_t)b * Tz * Dz + d;
        __half* wxb = g_wx + (size_t)b * Tz * Dz + d;
#pragma unroll 4
        for (int t = 0; t < Tz; t++) {
            float v = xb[(size_t)t * Dz] * a;
            owb[(size_t)t * Dz] = v;
            wxb[(size_t)t * Dz] = __float2half_rn(v);
        }
    } else if (bid < Bz + 2048) {
        // ---- weight prep: interleave rows (nr = (u/8)*32 + g*8 + u%8), fp16 ----
        int i = (bid - Bz) * 512 + tid;          // 0 .. 1M-1
        int row = i >> 9;
        int k = i & 511;
        int g = row >> 9;
        int u = row & 511;
        int nr = ((u >> 3) << 5) + (g << 3) + (u & 7);
        g_wih[nr * 512 + k] = __float2half_rn(wih[i]);
        g_whh[nr * 512 + k] = __float2half_rn(whh[i]);
        if (i < G4) {
            int gg = i >> 9, uu = i & 511;
            int nb = ((uu >> 3) << 5) + (gg << 3) + (uu & 7);
            g_bias[nb] = bih[i] + bhh[i];
        }
    } else {
        // ---- init h buffer 0 + flags ----
        int i = (bid - Bz - 2048) * 512 + tid;   // 0 .. Bz*Hz-1
        g_h2[i] = __float2half(0.f);
        if (i < 128) g_flag[i] = 0u;
        if (i < 8192) g_gxflag[i] = 0u;
    }
}

// ---------------- unified 128x128x512 mainloop (x workers) ----------------
__device__ __forceinline__ void mainloop(char* smem, int tid, int lane, int wm, int wn,
                                         const __half* Ab, long arst, const __half* Bb,
                                         float (&acc)[4][4][4]) {
    const int swl = (lane >> 1) & 3;
    const int swb = ((lane & 7) >> 1) & 3;

    auto pref = [&](int cj, int st) {
        int k0 = cj * 32;
        char* sb = smem + st * STG_SZ;
#pragma unroll
        for (int jj = 0; jj < 2; jj++) {
            int ci = tid * 2 + jj;
            int row = ci >> 2, c16 = ci & 3;
            int sw = (row >> 1) & 3;
            uint32_t soff = (uint32_t)(row * 64 + ((c16 ^ sw) << 4));
            CP_ASYNC16(smem_u32(sb + soff), Ab + (long)row * arst + k0 + c16 * 8);
            CP_ASYNC16(smem_u32(sb + 8192 + soff), Bb + (long)row * 512 + k0 + c16 * 8);
        }
    };

    pref(0, 0);
    CP_COMMIT();
    pref(1, 1);
    CP_COMMIT();

#pragma unroll
    for (int a = 0; a < 4; a++)
#pragma unroll
        for (int b = 0; b < 4; b++)
#pragma unroll
            for (int c = 0; c < 4; c++) acc[a][b][c] = 0.f;

    int stage = 0;
    for (int j = 0; j < 16; j++) {
        if (j < 15) { CP_WAIT(1); } else { CP_WAIT(0); }
        __syncthreads();
        if (j + 2 < 16) {
            int ns = stage + 2;
            if (ns >= 3) ns -= 3;
            pref(j + 2, ns);
            CP_COMMIT();
        }
        char* sa = smem + stage * STG_SZ;
#pragma unroll
        for (int kk = 0; kk < 2; kk++) {
            uint32_t av[4][4], bq[2][4];
#pragma unroll
            for (int mi = 0; mi < 4; mi++) {
                int row = wm * 64 + (lane & 15) + mi * 16;
                int c16 = (lane >> 4) + kk * 2;
                LDSM4(av[mi], smem_u32(sa + row * 64 + ((c16 ^ swl) << 4)));
            }
#pragma unroll
            for (int p = 0; p < 2; p++) {
                int row = wn * 32 + (lane >> 4) * 8 + (lane & 7) + p * 16;
                int c16 = kk * 2 + ((lane >> 3) & 1);
                LDSM4(bq[p], smem_u32(sa + 8192 + row * 64 + ((c16 ^ swb) << 4)));
            }
#pragma unroll
            for (int mi = 0; mi < 4; mi++)
#pragma unroll
                for (int ni = 0; ni < 4; ni++)
                    MMA(acc[mi][ni], av[mi], bq[ni >> 1][(ni & 1) * 2], bq[ni >> 1][(ni & 1) * 2 + 1]);
        }
        if (++stage == 3) stage = 0;
    }
    __syncthreads();
}

// ---------------- heterogeneous persistent kernel: 128 rec CTAs + 168 gemx CTAs ----------------
__global__ void __launch_bounds__(256, 2)
fused_enc(float* __restrict__ out_enc) {
    extern __shared__ char smem[];
    const int tid = threadIdx.x;
    const int lane = tid & 31, wid = tid >> 5;
    const int wm = wid >> 2, wn = wid & 3;
    const int bid = blockIdx.x;

    float acc[4][4][4];

    if (bid >= 128) {
        // ================= x-GEMM worker: t-major gx tiles =================
        for (int idx = bid - 128; idx < 8192; idx += N_XCTA) {
            int t = idx >> 7;
            int r = idx & 127;
            int tb = r >> 4, bnx = r & 15;

            const __half* A = g_wx + ((size_t)(tb * 128) * Tz + t) * Dz;
            const __half* B = g_wih + (size_t)bnx * 128 * 512;
            mainloop(smem, tid, lane, wm, wn, A, (long)Tz * Dz, B, acc);

#pragma unroll
            for (int ni = 0; ni < 4; ni++) {
                int c = bnx * 128 + wn * 32 + ni * 8 + (lane & 3) * 2;
                float2 bi = *(const float2*)(g_bias + c);
#pragma unroll
                for (int mi = 0; mi < 4; mi++) {
                    int rloc = wm * 64 + mi * 16 + (lane >> 2);
                    size_t r0 = ((size_t)(tb * 128 + rloc) * Tz + t) * G4 + c;
                    size_t r1 = ((size_t)(tb * 128 + rloc + 8) * Tz + t) * G4 + c;
                    st_cs_u32(g_gx16 + r0, pack_h2(acc[mi][ni][0] + bi.x, acc[mi][ni][1] + bi.y));
                    st_cs_u32(g_gx16 + r1, pack_h2(acc[mi][ni][2] + bi.x, acc[mi][ni][3] + bi.y));
                }
            }
            __syncthreads();
            if (tid == 0) red_rel_add(&g_gxflag[idx], 1u);
        }
        return;
    }

    // ================= persistent recurrence CTA =================
    const int bn = bid & 15, bm = bid >> 4;
    const int U = (bn * 4 + wn) * 8 + (lane & 3) * 2;
    const __half* Bh = g_whh + (size_t)bn * 128 * 512;
    const int swl = (lane >> 1) & 3;
    const int swb = ((lane & 7) >> 1) & 3;

    auto pref_gx = [&](int t) {
        char* gb = smem + RGX_OFF;
#pragma unroll
        for (int q = 0; q < 8; q++) {
            int ci = tid + q * 256;
            int row = ci >> 4, c = ci & 15;
            const void* g = g_gx16 + ((size_t)(bm * 128 + row) * Tz + t) * G4 + bn * 128 + c * 8;
            CP_ASYNC16(smem_u32(gb + row * RGXP + c * 16), g);
        }
    };

    // ---- OWN buffer init: A-half = h(0) = 0; B-half = W_hh chunk bn (loaded ONCE) ----
    {
        uint4 z = make_uint4(0u, 0u, 0u, 0u);
#pragma unroll
        for (int q = 0; q < 2; q++)
            *(uint4*)(smem + OWN_OFF + (tid + q * 256) * 16) = z;
#pragma unroll
        for (int jj = 0; jj < 2; jj++) {
            int ci = tid * 2 + jj;
            int row = ci >> 2, c16 = ci & 3;
            int sw = (row >> 1) & 3;
            CP_ASYNC16(smem_u32(smem + OWN_OFF + 8192 + row * 64 + ((c16 ^ sw) << 4)),
                       Bh + (long)row * 512 + bn * 32 + c16 * 8);
        }
        CP_COMMIT();
        CP_WAIT(0);
        __syncthreads();
    }

    float c_reg[4][2][2];
#pragma unroll
    for (int mi = 0; mi < 4; mi++)
#pragma unroll
        for (int h = 0; h < 2; h++) { c_reg[mi][h][0] = 0.f; c_reg[mi][h][1] = 0.f; }

    for (int t = 0; t < Tz; t++) {
        // ---- single merged wait phase: gx tile (tid16) + 15 peer h flags (tid<16) ----
        if (tid == 16) {
            while (ld_acq(&g_gxflag[t * 128 + bm * 16 + bn]) == 0) { }
        }
        if (t && tid < 16 && tid != bn) {
            while (ld_acq(&g_flag[bm * 16 + tid]) < (unsigned)t) { }
        }
        __syncthreads();

        const __half* A = g_h2 + (size_t)(t & 1) * Bz * Hz + (size_t)bm * 128 * Hz;
        auto pref_h = [&](int cj, int st) {
            int k0 = cj * 32;
            char* sb = smem + st * STG_SZ;
#pragma unroll
            for (int jj = 0; jj < 2; jj++) {
                int ci = tid * 2 + jj;
                int row = ci >> 2, c16 = ci & 3;
                int sw = (row >> 1) & 3;
                uint32_t soff = (uint32_t)(row * 64 + ((c16 ^ sw) << 4));
                CP_ASYNC16(smem_u32(sb + soff), A + (size_t)row * Hz + k0 + c16 * 8);
                CP_ASYNC16(smem_u32(sb + 8192 + soff), Bh + (long)row * 512 + k0 + c16 * 8);
            }
        };

        // groups: [gx] [chunk bn+1 -> st0] [chunk bn+2 -> st1]; OWN covers chunk bn
        pref_gx(t);
        CP_COMMIT();
        pref_h((bn + 1) & 15, 0);
        CP_COMMIT();
        pref_h((bn + 2) & 15, 1);
        CP_COMMIT();

#pragma unroll
        for (int a = 0; a < 4; a++)
#pragma unroll
            for (int b = 0; b < 4; b++)
#pragma unroll
                for (int c = 0; c < 4; c++) acc[a][b][c] = 0.f;

        // j=0: OWN buffer; j=1..15: chunk (bn+j) in stage (j-1)%3, prefetch depth 2
        for (int j = 0; j < 16; j++) {
            char* sa;
            if (j == 0) {
                sa = smem + OWN_OFF;
            } else {
                if (j < 15) { CP_WAIT(1); } else { CP_WAIT(0); }
                __syncthreads();
                if (j + 2 < 16) {
                    int ns = j + 1;
                    while (ns >= 3) ns -= 3;        // (j+1)%3
                    pref_h((bn + j + 2) & 15, ns);
                    CP_COMMIT();
                }
                int st = j - 1;
                while (st >= 3) st -= 3;            // (j-1)%3
                sa = smem + st * STG_SZ;
            }
#pragma unroll
            for (int kk = 0; kk < 2; kk++) {
                uint32_t av[4][4], bq[2][4];
#pragma unroll
                for (int mi = 0; mi < 4; mi++) {
                    int row = wm * 64 + (lane & 15) + mi * 16;
                    int c16 = (lane >> 4) + kk * 2;
                    LDSM4(av[mi], smem_u32(sa + row * 64 + ((c16 ^ swl) << 4)));
                }
#pragma unroll
                for (int p = 0; p < 2; p++) {
                    int row = wn * 32 + (lane >> 4) * 8 + (lane & 7) + p * 16;
                    int c16 = kk * 2 + ((lane >> 3) & 1);
                    LDSM4(bq[p], smem_u32(sa + 8192 + row * 64 + ((c16 ^ swb) << 4)));
                }
#pragma unroll
                for (int mi = 0; mi < 4; mi++)
#pragma unroll
                    for (int ni = 0; ni < 4; ni++)
                        MMA(acc[mi][ni], av[mi], bq[ni >> 1][(ni & 1) * 2], bq[ni >> 1][(ni & 1) * 2 + 1]);
            }
        }
        __syncthreads();   // mainloop done; OWN A-half free for epilogue refill

        // ---- fused LSTM epilogue (gx from smem, c in registers, HW tanh) ----
        // own h chunk written to OWN A-half (swizzled) AND global (for peers)
        __half* hw = g_h2 + (size_t)((t + 1) & 1) * Bz * Hz;
        char* gb = smem + RGX_OFF;
#pragma unroll
        for (int mi = 0; mi < 4; mi++) {
#pragma unroll
            for (int half = 0; half < 2; half++) {
                int mloc = wm * 64 + mi * 16 + half * 8 + (lane >> 2);
                int m = bm * 128 + mloc;
                int j0 = half * 2;
                const __half* gxr = (const __half*)(gb + mloc * RGXP) + wn * 32 + (lane & 3) * 2;
                float2 gI = __half22float2(*(const __half2*)(gxr + 0));
                float2 gF = __half22float2(*(const __half2*)(gxr + 8));
                float2 gG = __half22float2(*(const __half2*)(gxr + 16));
                float2 gO = __half22float2(*(const __half2*)(gxr + 24));
                float gi0 = acc[mi][0][j0] + gI.x, gi1 = acc[mi][0][j0 + 1] + gI.y;
                float gf0 = acc[mi][1][j0] + gF.x, gf1 = acc[mi][1][j0 + 1] + gF.y;
                float gg0 = acc[mi][2][j0] + gG.x, gg1 = acc[mi][2][j0 + 1] + gG.y;
                float go0 = acc[mi][3][j0] + gO.x, go1 = acc[mi][3][j0 + 1] + gO.y;
                float c20 = sigm(gf0) * c_reg[mi][half][0] + sigm(gi0) * tanh_f(gg0);
                float c21 = sigm(gf1) * c_reg[mi][half][1] + sigm(gi1) * tanh_f(gg1);
                c_reg[mi][half][0] = c20;
                c_reg[mi][half][1] = c21;
                float h20 = sigm(go0) * tanh_f(c20);
                float h21 = sigm(go1) * tanh_f(c21);
                st_cs_f2(out_enc + ((size_t)m * Tz + t) * Hz + U, h20, h21);
                __half2 hh = __floats2half2_rn(h20, h21);
                *(__half2*)(hw + (size_t)m * Hz + U) = hh;
                // own chunk -> OWN A-half, swizzled (c16 = wn, byte = (lane&3)*4)
                *(__half2*)(smem + OWN_OFF + mloc * 64 +
                            ((wn ^ ((mloc >> 1) & 3)) << 4) + (lane & 3) * 4) = hh;
            }
        }

        // ---- publish h(t+1): syncthreads + release-atomic ----
        __syncthreads();
        if (tid == 0) red_rel_add(&g_flag[bm * 16 + bn], 1u);
    }
}

// ---------------- launch ----------------
extern "C" void kernel_launch(void* const* d_in, const int* in_sizes, int n_in,
                              void* d_out, int out_size) {
    const float* x      = (const float*)d_in[0];
    const float* w_ih   = (const float*)d_in[1];
    const float* w_hh   = (const float*)d_in[2];
    const float* b_ih   = (const float*)d_in[3];
    const float* b_hh   = (const float*)d_in[4];
    const float* w_attn = (const float*)d_in[5];
    (void)in_sizes; (void)n_in; (void)out_size;

    float* out_w   = (float*)d_out;
    float* out_enc = out_w + (size_t)Bz * Tz * Dz;

    static int attr_done = 0;
    if (!attr_done) {
        cudaFuncSetAttribute(fused_enc, cudaFuncAttributeMaxDynamicSharedMemorySize, K_SMEM);
        attr_done = 1;
    }

    // merged pre-pass: attn+wx (1024) | weight prep (2048) | init (1024)
    pre_kernel<<<Bz + 2048 + 1024, 512>>>(x, w_attn, out_w, w_ih, w_hh, b_ih, b_hh);

    // heterogeneous persistent kernel: x-GEMM workers + recurrence, co-resident
    fused_enc<<<128 + N_XCTA, 256, K_SMEM>>>(out_enc);
}